// round 13
// baseline (speedup 1.0000x reference)
#include <cuda_runtime.h>
#include <cuda_bf16.h>

// Problem constants
#define Bz 4
#define Nz 128
#define Mz 128
#define Dz 256
#define BDz 1024

#define NDC 8                    // d-chunks (32 d each)
#define TSZ (Bz * Nz * Dz)       // 131072 elems per T partial
#define SSZ (Bz * Nz * Mz)       // 65536 elems (S)
#define KSPLIT 4                 // e-chunk split in the tail

// Scratch in device globals (no allocation allowed).
__device__ float g_Tp[NDC * TSZ];          // T partials over 8 d-chunks (4 MB)
__device__ float g_Sp[KSPLIT * SSZ];       // S partials over 4 e-chunks
__device__ int   g_cnt3[16];               // tail split-K epilogue tickets

// ---------------------------------------------------------------------------
// Kernel 1T: stream A once AND fold in both W-contraction and X-contraction.
// Grid: 256 blocks = 32 e-tiles (8 e each) x 8 d-chunks (32 d each).
// Phase 1 (per block): Aw[dl][el] = dot(A[d0+dl, e0+el, :1024], W)
//   - 256 rows, 8 warps, proven warp-dot inner loop; A slab is 32 KB-contig
//     chunks (8 e-rows) strided 1 MB; 268 MB total streamed once.
// Phase 2 (per block): Tp[dchunk][r, e0:e0+8] = sum_dl X[r, d0+dl]*Aw[dl][:]
//   - X is L2-resident (512 KB); adds ~16 MB L2 traffic total (+6%).
// Block 0 also resets the tail's ticket counters (stream order => replay-safe).
// ---------------------------------------------------------------------------
__global__ __launch_bounds__(256) void k1T(const float* __restrict__ A,
                                           const float* __restrict__ W,
                                           const float* __restrict__ X) {
    __shared__ float4 sW[BDz / 4];                 // 4 KB
    __shared__ __align__(16) float sAw[32][8];     // 1 KB  [d_local][e_local]

    int tid = threadIdx.x;
    int bid = blockIdx.x;
    if (bid == 0 && tid < 16) g_cnt3[tid] = 0;

    int etile  = bid >> 3;          // 0..31
    int dchunk = bid & 7;           // 0..7
    int e0 = etile * 8;
    int d0 = dchunk * 32;

    sW[tid] = reinterpret_cast<const float4*>(W)[tid];
    __syncthreads();

    int warp = tid >> 5;
    int lane = tid & 31;

    // ---- Phase 1: 256 (d,e) rows, 8 warps x 32 iterations ----
#pragma unroll 4
    for (int it = 0; it < 32; it++) {
        int row = it * 8 + warp;              // 0..255 = dl*8 + el
        int dl = row >> 3, el = row & 7;
        const float4* Arow = reinterpret_cast<const float4*>(A)
                           + ((long)(d0 + dl) * Dz + (e0 + el)) * (BDz / 4);
        float acc = 0.0f;
#pragma unroll
        for (int i = 0; i < 8; i++) {
            float4 a = Arow[i * 32 + lane];
            float4 w = sW[i * 32 + lane];
            acc += a.x * w.x + a.y * w.y + a.z * w.z + a.w * w.w;
        }
#pragma unroll
        for (int off = 16; off; off >>= 1)
            acc += __shfl_xor_sync(0xffffffffu, acc, off);
        if (lane == 0) sAw[dl][el] = acc;
    }
    __syncthreads();

    // ---- Phase 2: Tp partial. Thread = (g = tid>>1: 4 r-rows, eh = tid&1: e-quad)
    {
        int eh = tid & 1;                     // e-quad: e0 + eh*4 .. +3
        int g  = tid >> 1;                    // 0..127 -> r = g*4 + i
        const float4* X4 = reinterpret_cast<const float4*>(X);
        const float4* AwQ = reinterpret_cast<const float4*>(&sAw[0][0]) + eh;

#pragma unroll
        for (int i = 0; i < 4; i++) {
            int r = g * 4 + i;                // flattened (b,n) row, 0..511
            float4 acc = make_float4(0.f, 0.f, 0.f, 0.f);
#pragma unroll
            for (int d4 = 0; d4 < 8; d4++) {  // 4 d per iter, fixed order
                float4 xv = X4[(long)r * (Dz / 4) + dchunk * 8 + d4];
                float4 w0 = AwQ[(d4 * 4 + 0) * 2];
                float4 w1 = AwQ[(d4 * 4 + 1) * 2];
                float4 w2 = AwQ[(d4 * 4 + 2) * 2];
                float4 w3 = AwQ[(d4 * 4 + 3) * 2];
                acc.x += xv.x * w0.x + xv.y * w1.x + xv.z * w2.x + xv.w * w3.x;
                acc.y += xv.x * w0.y + xv.y * w1.y + xv.z * w2.y + xv.w * w3.y;
                acc.z += xv.x * w0.z + xv.y * w1.z + xv.z * w2.z + xv.w * w3.z;
                acc.w += xv.x * w0.w + xv.y * w1.w + xv.z * w2.w + xv.w * w3.w;
            }
            reinterpret_cast<float4*>(g_Tp)[((long)dchunk * 512 + r) * (Dz / 4)
                                            + (e0 >> 2) + eh] = acc;
        }
    }
}

// ---------------------------------------------------------------------------
// Tail: Sp[kse][b,n,m] = sum_{e in chunk} T[b,n,e]*Y[b,m,e]; T reconstructed
// from the 8 d-partials during the smem load (L2-hot). Last of the 4 e-chunk
// blocks per tile sums Sp in fixed order + bias -> S. Grid (2,2,16) = 64.
// ---------------------------------------------------------------------------
__global__ __launch_bounds__(256) void ktail(const float* __restrict__ Y,
                                             const float* __restrict__ bias,
                                             float* __restrict__ S) {
    __shared__ __align__(16) float sT[64][65];
    __shared__ __align__(16) float sY[64][65];
    __shared__ int sLast;

    int tid = threadIdx.x;
    int tx = tid & 15;            // m group
    int ty = tid >> 4;            // n group
    int m0 = blockIdx.x * 64;
    int n0 = blockIdx.y * 64;
    int b  = blockIdx.z >> 2;
    int kse = blockIdx.z & 3;
    int kc = kse * 64;            // e chunk
    int gid = (b * 2 + blockIdx.y) * 2 + blockIdx.x;   // 0..15

    long tb = (long)b * Nz * Dz;
    const float* Yb = Y + (long)b * Mz * Dz;

#pragma unroll
    for (int t = 0; t < 4; t++) {
        int lin = tid + t * 256;
        int row = lin >> 4;
        int c4  = (lin & 15) << 2;
        long base = tb + (long)(n0 + row) * Dz + kc + c4;
        float4 s = *reinterpret_cast<const float4*>(&g_Tp[0 * TSZ + base]);
#pragma unroll
        for (int dc = 1; dc < NDC; dc++) {   // fixed order => deterministic
            float4 tv = *reinterpret_cast<const float4*>(&g_Tp[(long)dc * TSZ + base]);
            s.x += tv.x; s.y += tv.y; s.z += tv.z; s.w += tv.w;
        }
        sT[row][c4 + 0] = s.x; sT[row][c4 + 1] = s.y;
        sT[row][c4 + 2] = s.z; sT[row][c4 + 3] = s.w;
        float4 yv = *reinterpret_cast<const float4*>(&Yb[(long)(m0 + row) * Dz + kc + c4]);
        sY[row][c4 + 0] = yv.x; sY[row][c4 + 1] = yv.y;
        sY[row][c4 + 2] = yv.z; sY[row][c4 + 3] = yv.w;
    }
    __syncthreads();

    float acc[4][4] = {};
#pragma unroll 16
    for (int e = 0; e < 64; e++) {
        float tv[4], yv[4];
#pragma unroll
        for (int i = 0; i < 4; i++) tv[i] = sT[ty + 16 * i][e];
#pragma unroll
        for (int j = 0; j < 4; j++) yv[j] = sY[tx + 16 * j][e];
#pragma unroll
        for (int i = 0; i < 4; i++)
#pragma unroll
            for (int j = 0; j < 4; j++)
                acc[i][j] += tv[i] * yv[j];
    }

    long sbase = (long)b * Nz * Mz;
    float* out = g_Sp + (long)kse * SSZ + sbase;
#pragma unroll
    for (int i = 0; i < 4; i++)
#pragma unroll
        for (int j = 0; j < 4; j++)
            out[(n0 + ty + 16 * i) * Mz + m0 + tx + 16 * j] = acc[i][j];

    // Fused deterministic split-K reduction: last of the 4 e-chunk blocks.
    __threadfence();
    __syncthreads();
    if (tid == 0) sLast = (atomicAdd(&g_cnt3[gid], 1) == KSPLIT - 1);
    __syncthreads();
    if (sLast) {
        float bv = bias[0];
#pragma unroll
        for (int t = 0; t < 4; t++) {
            int lin = tid + t * 256;
            int row = lin >> 4;
            int c4  = (lin & 15) << 2;
            long p = sbase + (long)(n0 + row) * Mz + m0 + c4;
            float4 a0 = *reinterpret_cast<const float4*>(&g_Sp[0 * SSZ + p]);
            float4 a1 = *reinterpret_cast<const float4*>(&g_Sp[1 * SSZ + p]);
            float4 a2 = *reinterpret_cast<const float4*>(&g_Sp[2 * SSZ + p]);
            float4 a3 = *reinterpret_cast<const float4*>(&g_Sp[3 * SSZ + p]);
            float4 r;
            r.x = a0.x + a1.x + a2.x + a3.x + bv;
            r.y = a0.y + a1.y + a2.y + a3.y + bv;
            r.z = a0.z + a1.z + a2.z + a3.z + bv;
            r.w = a0.w + a1.w + a2.w + a3.w + bv;
            *reinterpret_cast<float4*>(&S[p]) = r;
        }
    }
}

// ---------------------------------------------------------------------------
// Launch: inputs in order X, Y, A, W, b — two launches total.
// ---------------------------------------------------------------------------
extern "C" void kernel_launch(void* const* d_in, const int* in_sizes, int n_in,
                              void* d_out, int out_size) {
    const float* X = (const float*)d_in[0];  // [4,128,256]
    const float* Y = (const float*)d_in[1];  // [4,128,256]
    const float* A = (const float*)d_in[2];  // [256,256,1024]
    const float* W = (const float*)d_in[3];  // [1,1024]
    const float* b = (const float*)d_in[4];  // [1]
    float* S = (float*)d_out;                // [4,128,128]

    k1T<<<256, 256>>>(A, W, X);
    ktail<<<dim3(2, 2, 16), 256>>>(Y, b, S);
}